// round 10
// baseline (speedup 1.0000x reference)
#include <cuda_runtime.h>
#include <cuda_fp16.h>
#include <math.h>
#include <stdint.h>

// ---------------------------------------------------------------- constants
#define BSZ   16384
#define INSZ  512
#define OUTSZ 512
#define ORD   10
#define KTOT  5632              // 512 silu + 10*512 scrambled chebyshev
#define BM    64
#define BN    64
#define BK    64
#define NKT   (KTOT / BK)       // 88
#define STAGES 3
#define STAGE_BYTES 16384       // A 8KB + B 8KB
#define SMEM_BYTES  (STAGES * STAGE_BYTES)   // 49152 -> 4 CTAs/SM

// ---------------------------------------------------------------- scratch
__device__ __align__(16) __half g_a[(size_t)BSZ * KTOT];   // 176 MB
__device__ __align__(16) __half g_b[(size_t)OUTSZ * KTOT]; // 5.6 MB

// --------------------------------------------------------- merged builder
// blocks [0, BSZ):        Act rows (scrambled chebyshev + silu)
// blocks [BSZ, BSZ+5632): Wc, 512 elements per block
__global__ void build_all_kernel(const float* __restrict__ x,
                                 const float* __restrict__ base_w,
                                 const float* __restrict__ cheby_w) {
    int blk = blockIdx.x;
    int i   = threadIdx.x;                     // 0..511
    if (blk < BSZ) {
        int bb = blk;
        float xv = x[bb * INSZ + i];
        float s = xv / (1.0f + expf(-xv));
        g_a[(size_t)bb * KTOT + i] = __float2half_rn(s);

        float tm2 = 1.0f, tm1 = xv;
        #pragma unroll
        for (int o = 0; o < ORD; o++) {
            float t;
            if (o == 0)      t = 1.0f;
            else if (o == 1) t = xv;
            else { t = 2.0f * xv * tm1 - tm2; tm2 = tm1; tm1 = t; }
            int m  = o * BSZ + bb;
            int b  = m / 10;
            int op = m - b * 10;
            g_a[(size_t)b * KTOT + INSZ + op * INSZ + i] = __float2half_rn(t);
        }
    } else {
        int idx = (blk - BSZ) * 512 + i;
        int out = idx / KTOT;
        int k   = idx - out * KTOT;
        float v = (k < INSZ) ? base_w[out * INSZ + k]
                             : 0.1f * cheby_w[out * (INSZ * ORD) + (k - INSZ)];
        g_b[idx] = __float2half_rn(v);
    }
}

// --------------------------------------------------------- PTX primitives
__device__ __forceinline__ uint32_t smem_u32(const void* p) {
    uint32_t a;
    asm("{ .reg .u64 t; cvta.to.shared.u64 t, %1; cvt.u32.u64 %0, t; }" : "=r"(a) : "l"(p));
    return a;
}
__device__ __forceinline__ void cp16(uint32_t dst, const void* src) {
    asm volatile("cp.async.cg.shared.global [%0], [%1], 16;" :: "r"(dst), "l"(src));
}
#define LDSM_X4(d0, d1, d2, d3, addr)                                          \
    asm volatile("ldmatrix.sync.aligned.m8n8.x4.shared.b16 {%0,%1,%2,%3}, [%4];" \
                 : "=r"(d0), "=r"(d1), "=r"(d2), "=r"(d3) : "r"(addr))
#define HMMA(acc, a, b0, b1)                                                   \
    asm volatile("mma.sync.aligned.m16n8k16.row.col.f32.f16.f16.f32 "          \
                 "{%0,%1,%2,%3}, {%4,%5,%6,%7}, {%8,%9}, {%0,%1,%2,%3};"       \
                 : "+f"(acc[0]), "+f"(acc[1]), "+f"(acc[2]), "+f"(acc[3])      \
                 : "r"(a[0]), "r"(a[1]), "r"(a[2]), "r"(a[3]), "r"(b0), "r"(b1))

// ------------------------------------------------------------- HMMA GEMM
// C[16384,512] = A[16384,5632] @ B[512,5632]^T, fp16 in, fp32 accum.
// CTA 64x64, BK=64, 3-stage cp.async pipeline, 4 warps (2x2), 128 threads,
// warp tile 32x32. 4 CTAs/SM = 16 warps in 4 INDEPENDENT barrier domains
// (the R8 lesson: concurrency, not bytes/MAC, is the binding constraint).
__global__ void __launch_bounds__(128, 4) gemm_hmma_kernel(float* __restrict__ out) {
    extern __shared__ char smem[];
    uint32_t su = smem_u32(smem);
    int tid = threadIdx.x, lane = tid & 31, wid = tid >> 5;
    int mOff = (wid & 1) * 32;
    int nOff = (wid >> 1) * 32;
    int rowBase = blockIdx.y * BM;
    int colBase = blockIdx.x * BN;

    // loader mapping: threads 0-63 load A row tid, threads 64-127 B row tid-64,
    // each thread all 8 16B-chunks of its row (128 consecutive bytes in gmem).
    bool isA = tid < 64;
    int lrow = isA ? tid : (tid - 64);
    const __half* grow = (isA ? g_a + (size_t)(rowBase + lrow) * KTOT
                              : g_b + (size_t)(colBase + lrow) * KTOT);
    uint32_t dbase = (isA ? 0u : 8192u) + (uint32_t)lrow * 128;

    float acc[2][4][4];
    #pragma unroll
    for (int mi = 0; mi < 2; mi++)
        #pragma unroll
        for (int ni = 0; ni < 4; ni++)
            #pragma unroll
            for (int q = 0; q < 4; q++) acc[mi][ni][q] = 0.0f;

    int f_r = lane & 15, f_k = lane >> 4;   // ldmatrix x4 lane mapping

    uint32_t af[2][2][4];   // [buf][mi][4]
    uint32_t bf[2][2][4];   // [buf][npair][4]; regs {0,2}->ni even, {1,3}->ni odd

    // issue global loads for chunks 0, 1
    #pragma unroll
    for (int p = 0; p < 2; p++) {
        uint32_t sd = su + p * STAGE_BYTES + dbase;
        #pragma unroll
        for (int c = 0; c < 8; c++) {
            uint32_t off = (uint32_t)((c ^ (lrow & 7)) * 16);
            cp16(sd + off, grow + p * BK + c * 8);
        }
        asm volatile("cp.async.commit_group;" ::: "memory");
    }

    auto load_frags = [&](uint32_t sa, uint32_t sb, int ks, int bu) {
        int c = ks * 2 + f_k;
        #pragma unroll
        for (int mi = 0; mi < 2; mi++) {
            int r = mOff + mi * 16 + f_r;
            uint32_t ad = sa + (uint32_t)(r * 128 + ((c ^ (r & 7)) * 16));
            LDSM_X4(af[bu][mi][0], af[bu][mi][1], af[bu][mi][2], af[bu][mi][3], ad);
        }
        #pragma unroll
        for (int p = 0; p < 2; p++) {
            int r = nOff + p * 16 + f_r;
            uint32_t bd = sb + (uint32_t)(r * 128 + ((c ^ (r & 7)) * 16));
            LDSM_X4(bf[bu][p][0], bf[bu][p][1], bf[bu][p][2], bf[bu][p][3], bd);
        }
    };
    auto mma_step = [&](int bu) {
        #pragma unroll
        for (int mi = 0; mi < 2; mi++)
            #pragma unroll
            for (int p = 0; p < 2; p++) {
                HMMA(acc[mi][2 * p],     af[bu][mi], bf[bu][p][0], bf[bu][p][2]);
                HMMA(acc[mi][2 * p + 1], af[bu][mi], bf[bu][p][1], bf[bu][p][3]);
            }
    };

    // prologue: drain chunk 0, publish, load its ks0 fragments
    asm volatile("cp.async.wait_group 1;" ::: "memory");
    __syncthreads();
    load_frags(su, su + 8192, 0, 0);

    for (int kt = 0; kt < NKT; kt++) {
        uint32_t sa = su + (kt % STAGES) * STAGE_BYTES, sb = sa + 8192;

        #pragma unroll
        for (int ks = 0; ks < 3; ks++) {
            load_frags(sa, sb, ks + 1, (ks & 1) ^ 1);   // prefetch ks+1 frags
            mma_step(ks & 1);                            // MMA ks
        }

        // ---- transition (hidden under the trailing ks=3 MMAs) ----
        if (kt + 1 < NKT) {
            asm volatile("cp.async.wait_group 0;" ::: "memory");   // drain kt+1
            __syncthreads();
            uint32_t na = su + ((kt + 1) % STAGES) * STAGE_BYTES;
            load_frags(na, na + 8192, 0, 0);             // next chunk ks0 -> buf 0
            if (kt + 2 < NKT) {                          // issue chunk kt+2
                uint32_t pd = su + ((kt + 2) % STAGES) * STAGE_BYTES + dbase;
                #pragma unroll
                for (int c = 0; c < 8; c++) {
                    uint32_t off = (uint32_t)((c ^ (lrow & 7)) * 16);
                    cp16(pd + off, grow + (size_t)(kt + 2) * BK + c * 8);
                }
                asm volatile("cp.async.commit_group;" ::: "memory");
            }
        }

        mma_step(1);                                     // MMA ks=3 (buf 1)
    }

    // epilogue: C fragment layout -> float2 global stores
    int gid = lane >> 2, tig = lane & 3;
    #pragma unroll
    for (int mi = 0; mi < 2; mi++) {
        int r0 = rowBase + mOff + mi * 16 + gid;
        #pragma unroll
        for (int ni = 0; ni < 4; ni++) {
            int cc = colBase + nOff + ni * 8 + tig * 2;
            float2 v0 = make_float2(acc[mi][ni][0], acc[mi][ni][1]);
            float2 v1 = make_float2(acc[mi][ni][2], acc[mi][ni][3]);
            *(float2*)&out[(size_t)r0 * OUTSZ + cc]       = v0;
            *(float2*)&out[(size_t)(r0 + 8) * OUTSZ + cc] = v1;
        }
    }
}

// ----------------------------------------------------------------- launch
extern "C" void kernel_launch(void* const* d_in, const int* in_sizes, int n_in,
                              void* d_out, int out_size) {
    const float* x  = (const float*)d_in[0];   // (16384, 512)
    const float* bw = (const float*)d_in[1];   // (512, 512)
    const float* cw = (const float*)d_in[2];   // (512, 512, 10)
    float* out = (float*)d_out;

    cudaFuncSetAttribute(gemm_hmma_kernel,
                         cudaFuncAttributeMaxDynamicSharedMemorySize, SMEM_BYTES);

    build_all_kernel<<<BSZ + (OUTSZ * KTOT) / 512, 512>>>(x, bw, cw);

    dim3 grid(OUTSZ / BN, BSZ / BM);   // (8, 256)
    gemm_hmma_kernel<<<grid, 128, SMEM_BYTES>>>(out);
}

// round 12
// speedup vs baseline: 1.7679x; 1.7679x over previous
#include <cuda_runtime.h>
#include <cuda_fp16.h>
#include <math.h>
#include <stdint.h>

// ---------------------------------------------------------------- constants
#define BSZ   16384
#define INSZ  512
#define OUTSZ 512
#define ORD   10
#define KTOT  5632              // 512 silu + 10*512 scrambled chebyshev
#define BM    128
#define BN    128
#define BK    64
#define NKT   (KTOT / BK)       // 88
#define STAGES 3
#define STAGE_BYTES 32768       // A 16KB + B 16KB
#define SMEM_BYTES  (1024 + STAGES * STAGE_BYTES)   // 99328 -> 2 CTAs/SM

// ---------------------------------------------------------------- scratch
__device__ __align__(16) __half g_a[(size_t)BSZ * KTOT];   // 176 MB
__device__ __align__(16) __half g_b[(size_t)OUTSZ * KTOT]; // 5.6 MB

// --------------------------------------------------------- merged builder
// blocks [0, BSZ):        Act rows (scrambled chebyshev + silu)
// blocks [BSZ, BSZ+5632): Wc, 512 elements per block
__global__ void build_all_kernel(const float* __restrict__ x,
                                 const float* __restrict__ base_w,
                                 const float* __restrict__ cheby_w) {
    int blk = blockIdx.x;
    int i   = threadIdx.x;                     // 0..511
    if (blk < BSZ) {
        int bb = blk;
        float xv = x[bb * INSZ + i];
        float s = xv / (1.0f + expf(-xv));
        g_a[(size_t)bb * KTOT + i] = __float2half_rn(s);

        float tm2 = 1.0f, tm1 = xv;
        #pragma unroll
        for (int o = 0; o < ORD; o++) {
            float t;
            if (o == 0)      t = 1.0f;
            else if (o == 1) t = xv;
            else { t = 2.0f * xv * tm1 - tm2; tm2 = tm1; tm1 = t; }
            int m  = o * BSZ + bb;
            int b  = m / 10;
            int op = m - b * 10;
            g_a[(size_t)b * KTOT + INSZ + op * INSZ + i] = __float2half_rn(t);
        }
    } else {
        int idx = (blk - BSZ) * 512 + i;
        int out = idx / KTOT;
        int k   = idx - out * KTOT;
        float v = (k < INSZ) ? base_w[out * INSZ + k]
                             : 0.1f * cheby_w[out * (INSZ * ORD) + (k - INSZ)];
        g_b[idx] = __float2half_rn(v);
    }
}

// --------------------------------------------------------- PTX primitives
__device__ __forceinline__ uint32_t smem_u32(const void* p) {
    uint32_t a;
    asm("{ .reg .u64 t; cvta.to.shared.u64 t, %1; cvt.u32.u64 %0, t; }" : "=r"(a) : "l"(p));
    return a;
}
__device__ __forceinline__ void cp16(uint32_t dst, const void* src) {
    asm volatile("cp.async.cg.shared.global [%0], [%1], 16;" :: "r"(dst), "l"(src));
}
__device__ __forceinline__ void mbar_init(uint32_t mb, uint32_t cnt) {
    asm volatile("mbarrier.init.shared.b64 [%0], %1;" :: "r"(mb), "r"(cnt) : "memory");
}
__device__ __forceinline__ void mbar_arrive(uint32_t mb) {
    asm volatile("mbarrier.arrive.shared.b64 _, [%0];" :: "r"(mb) : "memory");
}
// .noinc is REQUIRED: the default form increments the pending count before
// arriving (net zero barrier progress) -> the R11 timeout.
__device__ __forceinline__ void cpasync_arrive(uint32_t mb) {
    asm volatile("cp.async.mbarrier.arrive.noinc.shared.b64 [%0];" :: "r"(mb) : "memory");
}
// bounded acquire parity wait (a logic bug becomes rel_err, not a timeout)
__device__ __forceinline__ void mbar_wait(uint32_t mb, uint32_t parity) {
    for (int i = 0; i < 1000000; i++) {
        uint32_t done;
        asm volatile(
            "{\n\t.reg .pred p;\n\t"
            "mbarrier.try_wait.parity.acquire.cta.shared::cta.b64 p, [%1], %2;\n\t"
            "selp.b32 %0, 1, 0, p;\n\t}"
            : "=r"(done) : "r"(mb), "r"(parity) : "memory");
        if (done) return;
    }
}
#define LDSM_X4(d0, d1, d2, d3, addr)                                          \
    asm volatile("ldmatrix.sync.aligned.m8n8.x4.shared.b16 {%0,%1,%2,%3}, [%4];" \
                 : "=r"(d0), "=r"(d1), "=r"(d2), "=r"(d3) : "r"(addr))
#define HMMA(acc, a, b0, b1)                                                   \
    asm volatile("mma.sync.aligned.m16n8k16.row.col.f32.f16.f16.f32 "          \
                 "{%0,%1,%2,%3}, {%4,%5,%6,%7}, {%8,%9}, {%0,%1,%2,%3};"       \
                 : "+f"(acc[0]), "+f"(acc[1]), "+f"(acc[2]), "+f"(acc[3])      \
                 : "r"(a[0]), "r"(a[1]), "r"(a[2]), "r"(a[3]), "r"(b0), "r"(b1))

// ------------------------------------------------------------- HMMA GEMM
// C[16384,512] = A[16384,5632] @ B[512,5632]^T, fp16 in, fp32 accum.
// R7 geometry (CTA 128x128, 8 warps 64x32, BK=64, 3 stages) with the
// block-wide rendezvous replaced by an mbarrier producer/consumer pipeline:
// full[s] flips via cp.async.mbarrier.arrive.noinc (256 thread-arrivals),
// empty[s] via explicit arrives after each thread's last fragment use.
// Warps drift up to ~1 chunk, decorrelating stalls across the SMSP.
__global__ void __launch_bounds__(256, 2) gemm_hmma_kernel(float* __restrict__ out) {
    extern __shared__ char smem[];
    uint32_t su = smem_u32(smem);
    int tid = threadIdx.x, lane = tid & 31, wid = tid >> 5;
    int mOff = (wid & 1) * 64;
    int nOff = (wid >> 1) * 32;
    int rowBase = blockIdx.y * BM;
    int colBase = blockIdx.x * BN;

    // barriers: full[s] = su + s*16, empty[s] = su + s*16 + 8
    if (tid == 0) {
        #pragma unroll
        for (int s = 0; s < STAGES; s++) {
            mbar_init(su + s * 16, 256);      // full: all threads' cp.async done
            mbar_init(su + s * 16 + 8, 256);  // empty: all threads done reading
        }
    }
    __syncthreads();   // the only block-wide barrier (init publish)

    const __half* Ag = g_a + (size_t)rowBase * KTOT;
    const __half* Bg = g_b + (size_t)colBase * KTOT;

    // loader mapping: 128 rows x 8 chunks(16B); 2 threads/row, 4 chunks each
    int lr  = tid >> 1;
    int lc4 = (tid & 1) * 4;
    const __half* agb = Ag + (size_t)lr * KTOT + lc4 * 8;
    const __half* bgb = Bg + (size_t)lr * KTOT + lc4 * 8;

    float acc[4][4][4];
    #pragma unroll
    for (int mi = 0; mi < 4; mi++)
        #pragma unroll
        for (int ni = 0; ni < 4; ni++)
            #pragma unroll
            for (int q = 0; q < 4; q++) acc[mi][ni][q] = 0.0f;

    int f_r = lane & 15, f_k = lane >> 4;   // ldmatrix x4 lane mapping

    uint32_t af[2][4][4];   // [buf][mi][4]
    uint32_t bf[2][2][4];   // [buf][npair][4]; regs {0,2}->ni even, {1,3}->ni odd

    // produce chunk pc into stage pc%3 (caller handles the empty-wait)
    auto produce = [&](int pc) {
        int s = pc % STAGES;
        uint32_t sa = su + 1024 + s * STAGE_BYTES, sb = sa + 16384;
        #pragma unroll
        for (int j = 0; j < 4; j++) {
            int c = lc4 + j;
            uint32_t off = (uint32_t)(lr * 128 + ((c ^ (lr & 7)) * 16));
            cp16(sa + off, agb + (size_t)pc * BK + j * 8);
            cp16(sb + off, bgb + (size_t)pc * BK + j * 8);
        }
        cpasync_arrive(su + s * 16);   // full[s] arrival when these complete
    };
    auto load_frags = [&](uint32_t sa, uint32_t sb, int ks, int bu) {
        int c = ks * 2 + f_k;
        #pragma unroll
        for (int mi = 0; mi < 4; mi++) {
            int r = mOff + mi * 16 + f_r;
            uint32_t ad = sa + (uint32_t)(r * 128 + ((c ^ (r & 7)) * 16));
            LDSM_X4(af[bu][mi][0], af[bu][mi][1], af[bu][mi][2], af[bu][mi][3], ad);
        }
        #pragma unroll
        for (int p = 0; p < 2; p++) {
            int r = nOff + p * 16 + f_r;
            uint32_t bd = sb + (uint32_t)(r * 128 + ((c ^ (r & 7)) * 16));
            LDSM_X4(bf[bu][p][0], bf[bu][p][1], bf[bu][p][2], bf[bu][p][3], bd);
        }
    };
    auto mma_step = [&](int bu) {
        #pragma unroll
        for (int mi = 0; mi < 4; mi++)
            #pragma unroll
            for (int p = 0; p < 2; p++) {
                HMMA(acc[mi][2 * p],     af[bu][mi], bf[bu][p][0], bf[bu][p][2]);
                HMMA(acc[mi][2 * p + 1], af[bu][mi], bf[bu][p][1], bf[bu][p][3]);
            }
    };

    // prologue: fill stages 0 and 1 (first use: no empty wait needed)
    produce(0);
    produce(1);

    for (int kt = 0; kt < NKT; kt++) {
        // ---- producer: chunk kt+2 ----
        if (kt + 2 < NKT) {
            int pc = kt + 2;
            if (pc >= STAGES) {
                // stage reused: wait until all threads consumed chunk pc-3
                // (that consumption is empty-flip index pc/3 - 1)
                int j = pc / STAGES - 1;
                mbar_wait(su + (pc % STAGES) * 16 + 8, (uint32_t)(j & 1));
            }
            produce(pc);
        }

        // ---- consumer: chunk kt (full-flip index kt/3) ----
        int s = kt % STAGES;
        mbar_wait(su + s * 16, (uint32_t)((kt / STAGES) & 1));
        uint32_t sa = su + 1024 + s * STAGE_BYTES, sb = sa + 16384;

        load_frags(sa, sb, 0, 0);
        #pragma unroll
        for (int ks = 0; ks < 3; ks++) {
            load_frags(sa, sb, ks + 1, (ks & 1) ^ 1);   // prefetch ks+1 frags
            mma_step(ks & 1);                            // MMA ks
        }
        mma_step(1);                                     // MMA ks=3

        // this thread's LDSM results all consumed -> release the stage
        mbar_arrive(su + s * 16 + 8);                    // empty[s]
    }

    // epilogue: C fragment layout -> float2 global stores
    int gid = lane >> 2, tig = lane & 3;
    #pragma unroll
    for (int mi = 0; mi < 4; mi++) {
        int r0 = rowBase + mOff + mi * 16 + gid;
        #pragma unroll
        for (int ni = 0; ni < 4; ni++) {
            int cc = colBase + nOff + ni * 8 + tig * 2;
            float2 v0 = make_float2(acc[mi][ni][0], acc[mi][ni][1]);
            float2 v1 = make_float2(acc[mi][ni][2], acc[mi][ni][3]);
            *(float2*)&out[(size_t)r0 * OUTSZ + cc]       = v0;
            *(float2*)&out[(size_t)(r0 + 8) * OUTSZ + cc] = v1;
        }
    }
}

// ----------------------------------------------------------------- launch
extern "C" void kernel_launch(void* const* d_in, const int* in_sizes, int n_in,
                              void* d_out, int out_size) {
    const float* x  = (const float*)d_in[0];   // (16384, 512)
    const float* bw = (const float*)d_in[1];   // (512, 512)
    const float* cw = (const float*)d_in[2];   // (512, 512, 10)
    float* out = (float*)d_out;

    cudaFuncSetAttribute(gemm_hmma_kernel,
                         cudaFuncAttributeMaxDynamicSharedMemorySize, SMEM_BYTES);

    build_all_kernel<<<BSZ + (OUTSZ * KTOT) / 512, 512>>>(x, bw, cw);

    dim3 grid(OUTSZ / BN, BSZ / BM);   // (4, 128)
    gemm_hmma_kernel<<<grid, 256, SMEM_BYTES>>>(out);
}

// round 15
// speedup vs baseline: 1.9878x; 1.1244x over previous
#include <cuda_runtime.h>
#include <cuda_fp16.h>
#include <math.h>
#include <stdint.h>

// ---------------------------------------------------------------- constants
#define BSZ   16384
#define INSZ  512
#define OUTSZ 512
#define ORD   10
#define KTOT  5632              // 512 silu + 10*512 scrambled chebyshev
#define BM    128
#define BN    128
#define BK    64
#define NKT   (KTOT / BK)       // 88
#define STAGES 3
#define STAGE_BYTES 32768       // A 16KB + B 16KB
#define SMEM_BYTES  (STAGES * STAGE_BYTES)   // 98304

// ---------------------------------------------------------------- scratch
__device__ __align__(16) __half g_a[(size_t)BSZ * KTOT];   // 176 MB
__device__ __align__(16) __half g_b[(size_t)OUTSZ * KTOT]; // 5.6 MB

// pack 4 floats -> uint2 of 4 halves via __half2 (no under-aligned punning)
__device__ __forceinline__ uint2 pack4h(float a, float b, float c, float d) {
    __half2 lo = __floats2half2_rn(a, b);
    __half2 hi = __floats2half2_rn(c, d);
    uint2 r;
    r.x = *reinterpret_cast<const uint32_t*>(&lo);   // __half2 is 4-aligned
    r.y = *reinterpret_cast<const uint32_t*>(&hi);
    return r;
}

// --------------------------------------------------------- merged builder
// Vectorized: 128 threads/block, each thread owns 4 consecutive elements
// (float4 load, uint2 = 4xhalf store).
// blocks [0, BSZ):        Act row bb = blk (silu + 10 scrambled cheby rows)
// blocks [BSZ, BSZ+5632): Wc, 512 elements per block
__global__ void build_all_kernel(const float* __restrict__ x,
                                 const float* __restrict__ base_w,
                                 const float* __restrict__ cheby_w) {
    int blk = blockIdx.x;
    int t   = threadIdx.x;                     // 0..127
    if (blk < BSZ) {
        int bb = blk;
        int i0 = t * 4;
        float4 xv4 = *(const float4*)&x[bb * INSZ + i0];
        float xv[4] = {xv4.x, xv4.y, xv4.z, xv4.w};

        // silu
        float sl[4];
        #pragma unroll
        for (int q = 0; q < 4; q++) sl[q] = xv[q] / (1.0f + expf(-xv[q]));
        *(uint2*)&g_a[(size_t)bb * KTOT + i0] = pack4h(sl[0], sl[1], sl[2], sl[3]);

        // chebyshev recurrence on 4 lanes; scatter per order
        float tm2[4] = {1.0f, 1.0f, 1.0f, 1.0f};
        float tm1[4] = {xv[0], xv[1], xv[2], xv[3]};
        #pragma unroll
        for (int o = 0; o < ORD; o++) {
            float tv[4];
            #pragma unroll
            for (int q = 0; q < 4; q++) {
                if (o == 0)      tv[q] = 1.0f;
                else if (o == 1) tv[q] = xv[q];
                else { float tt = 2.0f * xv[q] * tm1[q] - tm2[q];
                       tm2[q] = tm1[q]; tm1[q] = tt; tv[q] = tt; }
            }
            int m  = o * BSZ + bb;
            int b  = m / 10;
            int op = m - b * 10;
            *(uint2*)&g_a[(size_t)b * KTOT + INSZ + op * INSZ + i0] =
                pack4h(tv[0], tv[1], tv[2], tv[3]);
        }
    } else {
        // Wc: blk-BSZ in [0,5632), 512 elems per block, 4 per thread
        int idx0 = (blk - BSZ) * 512 + t * 4;
        int out = idx0 / KTOT;
        int k   = idx0 - out * KTOT;           // 4-aligned; branch uniform per group
        float4 v4;
        if (k < INSZ) v4 = *(const float4*)&base_w[out * INSZ + k];
        else {
            v4 = *(const float4*)&cheby_w[out * (INSZ * ORD) + (k - INSZ)];
            v4.x *= 0.1f; v4.y *= 0.1f; v4.z *= 0.1f; v4.w *= 0.1f;
        }
        *(uint2*)&g_b[idx0] = pack4h(v4.x, v4.y, v4.z, v4.w);
    }
}

// --------------------------------------------------------- PTX primitives
__device__ __forceinline__ uint32_t smem_u32(const void* p) {
    uint32_t a;
    asm("{ .reg .u64 t; cvta.to.shared.u64 t, %1; cvt.u32.u64 %0, t; }" : "=r"(a) : "l"(p));
    return a;
}
__device__ __forceinline__ void cp16(uint32_t dst, const void* src) {
    asm volatile("cp.async.cg.shared.global [%0], [%1], 16;" :: "r"(dst), "l"(src));
}
#define LDSM_X4(d0, d1, d2, d3, addr)                                          \
    asm volatile("ldmatrix.sync.aligned.m8n8.x4.shared.b16 {%0,%1,%2,%3}, [%4];" \
                 : "=r"(d0), "=r"(d1), "=r"(d2), "=r"(d3) : "r"(addr))
#define HMMA(acc, a, b0, b1)                                                   \
    asm volatile("mma.sync.aligned.m16n8k16.row.col.f32.f16.f16.f32 "          \
                 "{%0,%1,%2,%3}, {%4,%5,%6,%7}, {%8,%9}, {%0,%1,%2,%3};"       \
                 : "+f"(acc[0]), "+f"(acc[1]), "+f"(acc[2]), "+f"(acc[3])      \
                 : "r"(a[0]), "r"(a[1]), "r"(a[2]), "r"(a[3]), "r"(b0), "r"(b1))

// ------------------------------------------------------------- HMMA GEMM
// R7 kernel, verbatim (fastest measured: 395us GEMM).
// CTA 128x128, BK=64, 3-stage cp.async pipeline, 8 warps (2m x 4n),
// warp tile 64x32; chunk transition placed between ks=2 and ks=3.
__global__ void __launch_bounds__(256, 2) gemm_hmma_kernel(float* __restrict__ out) {
    extern __shared__ char smem[];
    uint32_t su = smem_u32(smem);
    int tid = threadIdx.x, lane = tid & 31, wid = tid >> 5;
    int mOff = (wid & 1) * 64;
    int nOff = (wid >> 1) * 32;
    int rowBase = blockIdx.y * BM;
    int colBase = blockIdx.x * BN;

    const __half* Ag = g_a + (size_t)rowBase * KTOT;
    const __half* Bg = g_b + (size_t)colBase * KTOT;

    int lr  = tid >> 1;
    int lc4 = (tid & 1) * 4;
    const __half* agb = Ag + (size_t)lr * KTOT + lc4 * 8;
    const __half* bgb = Bg + (size_t)lr * KTOT + lc4 * 8;

    float acc[4][4][4];
    #pragma unroll
    for (int mi = 0; mi < 4; mi++)
        #pragma unroll
        for (int ni = 0; ni < 4; ni++)
            #pragma unroll
            for (int q = 0; q < 4; q++) acc[mi][ni][q] = 0.0f;

    int f_r = lane & 15, f_k = lane >> 4;

    uint32_t af[2][4][4];
    uint32_t bf[2][2][4];

    #pragma unroll
    for (int p = 0; p < 2; p++) {
        uint32_t sa = su + p * STAGE_BYTES, sb = sa + 16384;
        #pragma unroll
        for (int j = 0; j < 4; j++) {
            int c = lc4 + j;
            uint32_t off = (uint32_t)(lr * 128 + ((c ^ (lr & 7)) * 16));
            cp16(sa + off, agb + p * BK + j * 8);
            cp16(sb + off, bgb + p * BK + j * 8);
        }
        asm volatile("cp.async.commit_group;" ::: "memory");
    }

    auto load_frags = [&](uint32_t sa, uint32_t sb, int ks, int bu) {
        int c = ks * 2 + f_k;
        #pragma unroll
        for (int mi = 0; mi < 4; mi++) {
            int r = mOff + mi * 16 + f_r;
            uint32_t ad = sa + (uint32_t)(r * 128 + ((c ^ (r & 7)) * 16));
            LDSM_X4(af[bu][mi][0], af[bu][mi][1], af[bu][mi][2], af[bu][mi][3], ad);
        }
        #pragma unroll
        for (int p = 0; p < 2; p++) {
            int r = nOff + p * 16 + f_r;
            uint32_t bd = sb + (uint32_t)(r * 128 + ((c ^ (r & 7)) * 16));
            LDSM_X4(bf[bu][p][0], bf[bu][p][1], bf[bu][p][2], bf[bu][p][3], bd);
        }
    };
    auto mma_step = [&](int bu) {
        #pragma unroll
        for (int mi = 0; mi < 4; mi++)
            #pragma unroll
            for (int p = 0; p < 2; p++) {
                HMMA(acc[mi][2 * p],     af[bu][mi], bf[bu][p][0], bf[bu][p][2]);
                HMMA(acc[mi][2 * p + 1], af[bu][mi], bf[bu][p][1], bf[bu][p][3]);
            }
    };

    asm volatile("cp.async.wait_group 1;" ::: "memory");
    __syncthreads();
    load_frags(su, su + 16384, 0, 0);

    for (int kt = 0; kt < NKT; kt++) {
        uint32_t sa = su + (kt % STAGES) * STAGE_BYTES, sb = sa + 16384;

        #pragma unroll
        for (int ks = 0; ks < 3; ks++) {
            load_frags(sa, sb, ks + 1, (ks & 1) ^ 1);
            mma_step(ks & 1);
        }

        if (kt + 1 < NKT) {
            asm volatile("cp.async.wait_group 0;" ::: "memory");
            __syncthreads();
            uint32_t na = su + ((kt + 1) % STAGES) * STAGE_BYTES, nb = na + 16384;
            load_frags(na, nb, 0, 0);
            if (kt + 2 < NKT) {
                uint32_t pa = su + ((kt + 2) % STAGES) * STAGE_BYTES, pb = pa + 16384;
                #pragma unroll
                for (int j = 0; j < 4; j++) {
                    int c = lc4 + j;
                    uint32_t off = (uint32_t)(lr * 128 + ((c ^ (lr & 7)) * 16));
                    cp16(pa + off, agb + (size_t)(kt + 2) * BK + j * 8);
                    cp16(pb + off, bgb + (size_t)(kt + 2) * BK + j * 8);
                }
                asm volatile("cp.async.commit_group;" ::: "memory");
            }
        }

        mma_step(1);
    }

    int gid = lane >> 2, tig = lane & 3;
    #pragma unroll
    for (int mi = 0; mi < 4; mi++) {
        int r0 = rowBase + mOff + mi * 16 + gid;
        #pragma unroll
        for (int ni = 0; ni < 4; ni++) {
            int cc = colBase + nOff + ni * 8 + tig * 2;
            float2 v0 = make_float2(acc[mi][ni][0], acc[mi][ni][1]);
            float2 v1 = make_float2(acc[mi][ni][2], acc[mi][ni][3]);
            *(float2*)&out[(size_t)r0 * OUTSZ + cc]       = v0;
            *(float2*)&out[(size_t)(r0 + 8) * OUTSZ + cc] = v1;
        }
    }
}

// ----------------------------------------------------------------- launch
extern "C" void kernel_launch(void* const* d_in, const int* in_sizes, int n_in,
                              void* d_out, int out_size) {
    const float* x  = (const float*)d_in[0];   // (16384, 512)
    const float* bw = (const float*)d_in[1];   // (512, 512)
    const float* cw = (const float*)d_in[2];   // (512, 512, 10)
    float* out = (float*)d_out;

    cudaFuncSetAttribute(gemm_hmma_kernel,
                         cudaFuncAttributeMaxDynamicSharedMemorySize, SMEM_BYTES);

    // 16384 Act blocks + 5632 Wc blocks, 128 threads each
    build_all_kernel<<<BSZ + OUTSZ * KTOT / 512, 128>>>(x, bw, cw);

    dim3 grid(OUTSZ / BN, BSZ / BM);   // (4, 128)
    gemm_hmma_kernel<<<grid, 256, SMEM_BYTES>>>(out);
}